// round 1
// baseline (speedup 1.0000x reference)
#include <cuda_runtime.h>

// out[b,i,j,f] = x[b,i,f] * y[b,j,f]; second half of d_out = 0.75 * first half.
// x,y: [B,3,128] fp32 (trailing dim 1 squeezed). out: [B,3,3,128] twice.
// Pure bandwidth problem: 307MB read + 922MB write.

__global__ __launch_bounds__(256)
void tp_kernel(const float4* __restrict__ x,
               const float4* __restrict__ y,
               float4* __restrict__ out,
               int B)
{
    int idx = blockIdx.x * blockDim.x + threadIdx.x;
    int total = B * 32;                 // 32 float4-groups of f per b
    if (idx >= total) return;

    int b  = idx >> 5;
    int f4 = idx & 31;

    // x[b][i][f]: float4 index (b*3 + i)*32 + f4
    float4 xv[3], yv[3];
#pragma unroll
    for (int i = 0; i < 3; i++) {
        xv[i] = x[(size_t)(b * 3 + i) * 32 + f4];
        yv[i] = y[(size_t)(b * 3 + i) * 32 + f4];
    }

    const size_t half = (size_t)B * 9 * 32;   // float4 elements in first output

#pragma unroll
    for (int i = 0; i < 3; i++) {
#pragma unroll
        for (int j = 0; j < 3; j++) {
            float4 p;
            p.x = xv[i].x * yv[j].x;
            p.y = xv[i].y * yv[j].y;
            p.z = xv[i].z * yv[j].z;
            p.w = xv[i].w * yv[j].w;
            size_t o = ((size_t)b * 9 + i * 3 + j) * 32 + f4;
            out[o] = p;
            float4 q;
            q.x = 0.75f * p.x;
            q.y = 0.75f * p.y;
            q.z = 0.75f * p.z;
            q.w = 0.75f * p.w;
            out[half + o] = q;
        }
    }
}

extern "C" void kernel_launch(void* const* d_in, const int* in_sizes, int n_in,
                              void* d_out, int out_size)
{
    const float4* x = (const float4*)d_in[0];
    const float4* y = (const float4*)d_in[1];
    float4* out = (float4*)d_out;

    int B = in_sizes[0] / (3 * 128);    // 100000
    int total = B * 32;
    int threads = 256;
    int blocks = (total + threads - 1) / threads;
    tp_kernel<<<blocks, threads>>>(x, y, out, B);
}